// round 16
// baseline (speedup 1.0000x reference)
#include <cuda_runtime.h>
#include <cuda_bf16.h>

typedef unsigned int u32;
typedef unsigned short u16;

#define B_   64
#define T_   512
#define D_   256
#define U_   512
#define G3   1536
#define NBLK 64
#define NTHR 512
#define SCAN_SMEM 230400
#define INPROJ_SMEM 98304

// ---------------- device scratch (no allocations allowed) ----------------
__device__ float g_gx[(size_t)2 * T_ * B_ * G3];   // [dir][t][b][3U]
// bf16-split state images (ldmatrix-swizzled): [dir][64KB]
__device__ __align__(16) unsigned char g_h1[2][65536];
__device__ __align__(16) unsigned char g_h2[2][65536];
__device__ __align__(16) unsigned char g_r1[2][65536];
__device__ __align__(16) unsigned char g_r2[2][65536];
// bf16-split inproj operand images
__device__ __align__(16) unsigned char g_x1[(size_t)32768 * 512];  // 16MB
__device__ __align__(16) unsigned char g_x2[(size_t)32768 * 512];
__device__ __align__(16) unsigned char g_w1[(size_t)3072 * 512];   // 1.5MB
__device__ __align__(16) unsigned char g_w2[(size_t)3072 * 512];
__device__ unsigned          g_barc[2] = {0, 0};
__device__ volatile unsigned g_barg[2] = {0, 0};

// Per-direction software barrier over 32 blocks (replay-safe; busy spin).
__device__ __forceinline__ void dir_barrier(int dir) {
    __threadfence();
    __syncthreads();
    if (threadIdx.x == 0) {
        unsigned g = g_barg[dir];
        unsigned prev = atomicAdd(&g_barc[dir], 1u);
        if (prev == 31u) {
            g_barc[dir] = 0u;
            __threadfence();
            g_barg[dir] = g + 1u;
        } else {
            while (g_barg[dir] == g) { }
        }
    }
    __syncthreads();
}

__device__ __forceinline__ float sigmoidf_(float z) {
    return 1.0f / (1.0f + __expf(-z));
}
__device__ __forceinline__ u32 smem_u32(const void* p) {
    u32 a;
    asm("{ .reg .u64 t; cvta.to.shared.u64 t, %1; cvt.u32.u64 %0, t; }"
        : "=r"(a) : "l"(p));
    return a;
}
// 1KB-row image offset (512 bf16/row), XOR swizzle on 16B chunks
__device__ __forceinline__ u32 off_(u32 row, u32 k) {
    u32 c = k >> 3;
    c = (c & ~7u) | ((c ^ row) & 7u);
    return row * 1024u + c * 16u + (k & 7u) * 2u;
}
// 512B-row image (256 bf16/row)
__device__ __forceinline__ u32 off512_(u32 row, u32 k) {
    u32 c = k >> 3;
    c = (c & ~7u) | ((c ^ row) & 7u);
    return row * 512u + c * 16u + (k & 7u) * 2u;
}
__device__ __forceinline__ void ldm4(u32* r, u32 addr) {
    asm volatile("ldmatrix.sync.aligned.m8n8.x4.shared.b16 {%0,%1,%2,%3}, [%4];"
        : "=r"(r[0]), "=r"(r[1]), "=r"(r[2]), "=r"(r[3]) : "r"(addr));
}
__device__ __forceinline__ void ldm2(u32* r, u32 addr) {
    asm volatile("ldmatrix.sync.aligned.m8n8.x2.shared.b16 {%0,%1}, [%2];"
        : "=r"(r[0]), "=r"(r[1]) : "r"(addr));
}
__device__ __forceinline__ void mma_bf16(float* d, const u32* a, const u32* b) {
    asm volatile("mma.sync.aligned.m16n8k16.row.col.f32.bf16.bf16.f32 "
        "{%0,%1,%2,%3}, {%4,%5,%6,%7}, {%8,%9}, {%0,%1,%2,%3};"
        : "+f"(d[0]), "+f"(d[1]), "+f"(d[2]), "+f"(d[3])
        : "r"(a[0]), "r"(a[1]), "r"(a[2]), "r"(a[3]), "r"(b[0]), "r"(b[1]));
}
__device__ __forceinline__ void split_bf16(float x, u16& hi, u16& lo) {
    __nv_bfloat16 h = __float2bfloat16(x);
    __nv_bfloat16 l = __float2bfloat16(x - __bfloat162float(h));
    hi = __bfloat16_as_ushort(h);
    lo = __bfloat16_as_ushort(l);
}
__device__ __forceinline__ float join_bf16(const void* p1, const void* p2) {
    return __bfloat162float(__ushort_as_bfloat16(*(const u16*)p1)) +
           __bfloat162float(__ushort_as_bfloat16(*(const u16*)p2));
}
#define CP16(dst, src) \
    asm volatile("cp.async.cg.shared.global [%0], [%1], 16;" :: "r"(dst), "l"(src) : "memory")
#define CP_COMMIT() asm volatile("cp.async.commit_group;" ::: "memory")
#define CP_WAIT0()  asm volatile("cp.async.wait_group 0;" ::: "memory")
#define CP_WAIT1()  asm volatile("cp.async.wait_group 1;" ::: "memory")

// =====================================================================
// Prep kernels: split x and [Wx_f | Wx_b] into bf16 hi/lo images.
// =====================================================================
__global__ void __launch_bounds__(256) k_split_x(const float* __restrict__ x)
{
    int idx = blockIdx.x * 256 + threadIdx.x;
    int m = idx >> 5, c = idx & 31, k0 = c * 8;
    const float* src = x + (size_t)m * 256 + k0;
    float4 f0 = __ldg((const float4*)src);
    float4 f1 = __ldg((const float4*)(src + 4));
    float e[8] = {f0.x, f0.y, f0.z, f0.w, f1.x, f1.y, f1.z, f1.w};
    u16 h[8], l[8];
#pragma unroll
    for (int j = 0; j < 8; j++) split_bf16(e[j], h[j], l[j]);
    uint4 H = make_uint4(h[0] | (h[1] << 16), h[2] | (h[3] << 16),
                         h[4] | (h[5] << 16), h[6] | (h[7] << 16));
    uint4 L = make_uint4(l[0] | (l[1] << 16), l[2] | (l[3] << 16),
                         l[4] | (l[5] << 16), l[6] | (l[7] << 16));
    u32 o = off512_((u32)m, (u32)k0);
    *(uint4*)(g_x1 + o) = H;
    *(uint4*)(g_x2 + o) = L;
}

__global__ void __launch_bounds__(256) k_split_w(
    const float* __restrict__ Wxf, const float* __restrict__ Wxb)
{
    int n = blockIdx.x * 256 + threadIdx.x;
    int dir = (n >= G3) ? 1 : 0;
    int col = n - dir * G3;
    const float* W = dir ? Wxb : Wxf;
    for (int c = 0; c < 32; c++) {
        u16 h[8], l[8];
#pragma unroll
        for (int j = 0; j < 8; j++)
            split_bf16(__ldg(W + (size_t)(c * 8 + j) * G3 + col), h[j], l[j]);
        uint4 H = make_uint4(h[0] | (h[1] << 16), h[2] | (h[3] << 16),
                             h[4] | (h[5] << 16), h[6] | (h[7] << 16));
        uint4 L = make_uint4(l[0] | (l[1] << 16), l[2] | (l[3] << 16),
                             l[4] | (l[5] << 16), l[6] | (l[7] << 16));
        u32 o = off512_((u32)n, (u32)(c * 8));
        *(uint4*)(g_w1 + o) = H;
        *(uint4*)(g_w2 + o) = L;
    }
}

// =====================================================================
// Kernel A: input projections via bf16-split HMMA (R12-proven).
// =====================================================================
extern __shared__ char ipsm[];

__global__ void __launch_bounds__(NTHR, 1) k_inproj_mma(int dummy)
{
    const int tid  = threadIdx.x;
    const int wid  = tid >> 5;
    const int lane = tid & 31;
    const int m0   = blockIdx.x * 128;
    const int n0   = blockIdx.y * 64;
    const int wm   = wid & 3, wn = wid >> 2;

    const u32 sbase = smem_u32(ipsm);
    auto stage_load = [&](int kt, int s) {
        u32 b0 = sbase + (u32)s * 49152u;
#pragma unroll
        for (int i = 0; i < 6; i++) {
            int gid = tid + i * NTHR;
            if (gid < 2048) {
                int term = gid >> 10, row = (gid & 1023) >> 3, c = gid & 7;
                u32 dst = b0 + (u32)term * 16384u + (u32)(row * 128 + c * 16);
                const unsigned char* srcimg = term ? g_x2 : g_x1;
                CP16(dst, srcimg + (size_t)(m0 + row) * 512 + kt * 128 + c * 16);
            } else {
                int g2 = gid - 2048;
                int term = g2 >> 9, row = (g2 & 511) >> 3, c = g2 & 7;
                u32 dst = b0 + 32768u + (u32)term * 8192u + (u32)(row * 128 + c * 16);
                const unsigned char* srcimg = term ? g_w2 : g_w1;
                CP16(dst, srcimg + (size_t)(n0 + row) * 512 + kt * 128 + c * 16);
            }
        }
        CP_COMMIT();
    };

    float dhh[2][2][4], dlo[2][2][4];
#pragma unroll
    for (int mi = 0; mi < 2; mi++)
#pragma unroll
        for (int ni = 0; ni < 2; ni++)
#pragma unroll
            for (int q = 0; q < 4; q++) { dhh[mi][ni][q] = 0.f; dlo[mi][ni][q] = 0.f; }

    stage_load(0, 0);
    stage_load(1, 1);

    const u32 rA0 = (u32)(wm * 32 + (lane & 15));
    const u32 rA1 = rA0 + 16;
    const u32 nB0 = (u32)(wn * 16 + (lane & 7));
    const u32 nB1 = nB0 + 8;
    const u32 kq4 = (u32)(lane >> 4);
    const u32 kq2 = (u32)((lane >> 3) & 1);

    for (int kt = 0; kt < 4; kt++) {
        if (kt < 3) CP_WAIT1(); else CP_WAIT0();
        __syncthreads();
        u32 b0 = sbase + (u32)(kt & 1) * 49152u;
        u32 AhU = b0, AlU = b0 + 16384u, BhU = b0 + 32768u, BlU = b0 + 40960u;
#pragma unroll
        for (int ks = 0; ks < 4; ks++) {
            u32 ca = (u32)(2 * ks) + kq4;
            u32 ca0 = (ca ^ rA0) & 7u, ca1 = (ca ^ rA1) & 7u;
            u32 aH0[4], aH1[4], aL0[4], aL1[4];
            ldm4(aH0, AhU + rA0 * 128u + ca0 * 16u);
            ldm4(aH1, AhU + rA1 * 128u + ca1 * 16u);
            ldm4(aL0, AlU + rA0 * 128u + ca0 * 16u);
            ldm4(aL1, AlU + rA1 * 128u + ca1 * 16u);
            u32 cb = (u32)(2 * ks) + kq2;
            u32 cb0 = (cb ^ nB0) & 7u, cb1 = (cb ^ nB1) & 7u;
            u32 bH0[2], bH1[2], bL0[2], bL1[2];
            ldm2(bH0, BhU + nB0 * 128u + cb0 * 16u);
            ldm2(bH1, BhU + nB1 * 128u + cb1 * 16u);
            ldm2(bL0, BlU + nB0 * 128u + cb0 * 16u);
            ldm2(bL1, BlU + nB1 * 128u + cb1 * 16u);
            mma_bf16(dhh[0][0], aH0, bH0); mma_bf16(dhh[0][1], aH0, bH1);
            mma_bf16(dhh[1][0], aH1, bH0); mma_bf16(dhh[1][1], aH1, bH1);
            mma_bf16(dlo[0][0], aH0, bL0); mma_bf16(dlo[0][1], aH0, bL1);
            mma_bf16(dlo[1][0], aH1, bL0); mma_bf16(dlo[1][1], aH1, bL1);
            mma_bf16(dlo[0][0], aL0, bH0); mma_bf16(dlo[0][1], aL0, bH1);
            mma_bf16(dlo[1][0], aL1, bH0); mma_bf16(dlo[1][1], aL1, bH1);
        }
        __syncthreads();
        if (kt < 2) stage_load(kt + 2, kt & 1);
    }

#pragma unroll
    for (int mi = 0; mi < 2; mi++)
#pragma unroll
        for (int ni = 0; ni < 2; ni++) {
            int gm = m0 + wm * 32 + mi * 16 + (lane >> 2);
            int gc = n0 + wn * 16 + ni * 8 + (lane & 3) * 2;
            int dir = (gc >= G3) ? 1 : 0;
            int cc  = gc - dir * G3;
            int b   = gm >> 9;
#pragma unroll
            for (int half = 0; half < 2; half++) {
                int s = (gm + half * 8) & 511;
                int tt = dir ? (T_ - 1 - s) : s;
                float* d = g_gx + (((size_t)dir * T_ + tt) * B_ + b) * G3 + cc;
                *(float2*)d = make_float2(dhh[mi][ni][half * 2] + dlo[mi][ni][half * 2],
                                          dhh[mi][ni][half * 2 + 1] + dlo[mi][ni][half * 2 + 1]);
            }
        }
}

// =====================================================================
// Kernel B: persistent HMMA scan. 64 blocks (32/dir), 512 thr.
// Block rank owns 16 u + 16 r + 16 cand cols.
// Phase A: 16 warps = 4m x 4n, no K-split, 3 indep accumulator chains.
// Phase B: 16 warps = 2 k-halves x (4m x 2n); partials aliased into the
// dead A-image smem region. u/h_old register-resident across phases.
// =====================================================================
extern __shared__ char dynsm[];

__global__ void __launch_bounds__(NTHR, 1)
k_scan(const float* __restrict__ Whf, const float* __restrict__ Whb,
       const float* __restrict__ bf,  const float* __restrict__ bb,
       float* __restrict__ out)
{
    const int tid  = threadIdx.x;
    const int wid  = tid >> 5;
    const int lane = tid & 31;
    const int blk  = blockIdx.x;
    const int dir  = blk >> 5;
    const int rank = blk & 31;

    const float* __restrict__ Wh   = dir ? Whb : Whf;
    const float* __restrict__ bias = dir ? bb : bf;

    const u32 raw  = smem_u32(dynsm);
    const u32 base = (raw + 1023u) & ~1023u;
    char* dp = dynsm + (base - raw);
    char* A1 = dp;                  // 64KB state hi
    char* A2 = dp + 65536;          // 64KB state lo
    char* W1 = dp + 131072;         // 32KB phase-A weights hi (32 rows)
    char* W2 = dp + 163840;         // 32KB phase-A weights lo
    char* V1 = dp + 196608;         // 16KB phase-B weights hi (16 rows)
    char* V2 = dp + 212992;         // 16KB phase-B weights lo
    float* sPf = (float*)dp;        // phase-B partials alias (A image dead)
    const u32 A1u = base, A2u = base + 65536;
    const u32 W1u = base + 131072, W2u = base + 163840;
    const u32 V1u = base + 196608, V2u = base + 212992;

    // ---- split weight slices into smem (once) ----
    for (int i = tid; i < 32 * 512; i += NTHR) {
        int n = i >> 9, k = i & 511;
        int col = (n < 16) ? (rank * 16 + n) : (512 + rank * 16 + (n - 16));
        u16 hi, lo;
        split_bf16(__ldg(Wh + (size_t)k * G3 + col), hi, lo);
        u32 o = off_((u32)n, (u32)k);
        *(u16*)(W1 + o) = hi;
        *(u16*)(W2 + o) = lo;
    }
    for (int i = tid; i < 16 * 512; i += NTHR) {
        int n = i >> 9, k = i & 511;
        u16 hi, lo;
        split_bf16(__ldg(Wh + (size_t)k * G3 + 1024 + rank * 16 + n), hi, lo);
        u32 o = off_((u32)n, (u32)k);
        *(u16*)(V1 + o) = hi;
        *(u16*)(V2 + o) = lo;
    }

    // ---- warp mappings ----
    // Phase A: wid = nt*4 + mt (nt 0..3, mt 0..3); n-tile = nt*8 cols of 32
    const int ntA = wid >> 2, mtA = wid & 3;
    const u32 rA   = (u32)(mtA * 16 + (lane & 15));
    const u32 aRow = rA * 1024u;
    const u32 rxA  = rA & 7u;
    const u32 nA   = (u32)(ntA * 8 + (lane & 7));
    const u32 nRow = nA * 1024u;
    const u32 rxB  = nA & 7u;
    const u32 kq4  = (u32)(lane >> 4);
    const u32 kq2  = (u32)((lane >> 3) & 1);
    // Phase B: khB = wid>>3; within half: ntB = (wid&7)>>2, mtB = wid&3
    const int khB = wid >> 3;
    const int ntB = (wid & 7) >> 2, mtB = wid & 3;
    const u32 rB   = (u32)(mtB * 16 + (lane & 15));
    const u32 bRow = rB * 1024u;
    const u32 rxAB = rB & 7u;
    const u32 nV   = (u32)(ntB * 8 + (lane & 7));
    const u32 vRow = nV * 1024u;
    const u32 rxV  = nV & 7u;

    // epilogue rows/cols
    const int er0 = mtA * 16 + (lane >> 2);     // phase A rows (+8)
    const int ec0 = (lane & 3) * 2;
    const int clA = ntA * 8 + ec0;              // col-local 0..30 (even)
    const int erB = mtB * 16 + (lane >> 2);     // phase B rows (+8)
    const int clB = ntB * 8 + ec0;              // cand col-local 0..14

    const int gbaseA = (clA < 16) ? (rank * 16 + clA) : (512 + rank * 16 + clA - 16);
    const float2 biasA = *(const float2*)(bias + gbaseA);
    float2 biasC = make_float2(0.f, 0.f);
    if (wid < 8) biasC = *(const float2*)(bias + 1024 + rank * 16 + clB);

    float ureg[4], holdreg[4];
    const float* gx0 = g_gx + (size_t)dir * T_ * B_ * G3;

    for (int t = 0; t < T_; t++) {
        const float* gxt = gx0 + (size_t)t * B_ * G3;

        // ================= Phase A =================
        const float* gpA = gxt + (size_t)er0 * G3 + gbaseA;
        float2 gA0 = __ldg((const float2*)gpA);
        float2 gA1 = __ldg((const float2*)(gpA + (size_t)8 * G3));

        if (t == 0) {
            uint4 z0 = make_uint4(0, 0, 0, 0);
#pragma unroll
            for (int i = 0; i < 8; i++) {
                int idx = tid + i * NTHR;
                ((uint4*)A1)[idx] = z0;
                ((uint4*)A2)[idx] = z0;
            }
        } else {
#pragma unroll
            for (int i = 0; i < 8; i++) {
                u32 ch = (u32)(tid + i * NTHR) * 16u;
                CP16(A1u + ch, g_h1[dir] + ch);
                CP16(A2u + ch, g_h2[dir] + ch);
            }
            CP_COMMIT();
            CP_WAIT0();
        }
        __syncthreads();

        if (wid < 8) {   // u-warps double as phase-B epilogue owners
            u32 kc = (u32)(rank * 16 + clB);
            u32 o0 = off_((u32)erB, kc), o1 = off_((u32)(erB + 8), kc);
            holdreg[0] = join_bf16(A1 + o0, A2 + o0);
            holdreg[1] = join_bf16(A1 + o0 + 2, A2 + o0 + 2);
            holdreg[2] = join_bf16(A1 + o1, A2 + o1);
            holdreg[3] = join_bf16(A1 + o1 + 2, A2 + o1 + 2);
        }

        {
            float dhh[4] = {0, 0, 0, 0}, dhl[4] = {0, 0, 0, 0}, dlh[4] = {0, 0, 0, 0};
#pragma unroll 4
            for (int ks = 0; ks < 32; ks++) {
                u32 ca = (u32)(2 * ks) + kq4;
                u32 cas = (ca & ~7u) | ((ca ^ rxA) & 7u);
                u32 aH[4], aL[4], bH[2], bL[2];
                ldm4(aH, A1u + aRow + cas * 16u);
                ldm4(aL, A2u + aRow + cas * 16u);
                u32 cb = (u32)(2 * ks) + kq2;
                u32 cbs = (cb & ~7u) | ((cb ^ rxB) & 7u);
                ldm2(bH, W1u + nRow + cbs * 16u);
                ldm2(bL, W2u + nRow + cbs * 16u);
                mma_bf16(dhh, aH, bH);
                mma_bf16(dhl, aH, bL);
                mma_bf16(dlh, aL, bH);
            }
            float z0v = dhh[0] + dhl[0] + dlh[0];
            float z1v = dhh[1] + dhl[1] + dlh[1];
            float z2v = dhh[2] + dhl[2] + dlh[2];
            float z3v = dhh[3] + dhl[3] + dlh[3];

            if (clA < 16) {         // u gates -> registers
                ureg[0] = sigmoidf_(z0v + gA0.x + biasA.x);
                ureg[1] = sigmoidf_(z1v + gA0.y + biasA.y);
                ureg[2] = sigmoidf_(z2v + gA1.x + biasA.x);
                ureg[3] = sigmoidf_(z3v + gA1.y + biasA.y);
            } else {                // r gates -> rh image
                float r0v = sigmoidf_(z0v + gA0.x + biasA.x);
                float r1v = sigmoidf_(z1v + gA0.y + biasA.y);
                float r2v = sigmoidf_(z2v + gA1.x + biasA.x);
                float r3v = sigmoidf_(z3v + gA1.y + biasA.y);
                u32 krh = (u32)(rank * 16 + clA - 16);
                u32 o0 = off_((u32)er0, krh);
                u32 o1 = off_((u32)(er0 + 8), krh);
                float h00 = join_bf16(A1 + o0, A2 + o0);
                float h01 = join_bf16(A1 + o0 + 2, A2 + o0 + 2);
                float h10 = join_bf16(A1 + o1, A2 + o1);
                float h11 = join_bf16(A1 + o1 + 2, A2 + o1 + 2);
                u16 a_hi, a_lo, b_hi, b_lo;
                split_bf16(r0v * h00, a_hi, a_lo);
                split_bf16(r1v * h01, b_hi, b_lo);
                *(u32*)(g_r1[dir] + o0) = (u32)a_hi | ((u32)b_hi << 16);
                *(u32*)(g_r2[dir] + o0) = (u32)a_lo | ((u32)b_lo << 16);
                split_bf16(r2v * h10, a_hi, a_lo);
                split_bf16(r3v * h11, b_hi, b_lo);
                *(u32*)(g_r1[dir] + o1) = (u32)a_hi | ((u32)b_hi << 16);
                *(u32*)(g_r2[dir] + o1) = (u32)a_lo | ((u32)b_lo << 16);
            }
        }
        dir_barrier(dir);

        // ================= Phase B =================
        float2 gC0, gC1;
        if (wid < 8) {
            const float* gp = gxt + (size_t)erB * G3 + 1024 + rank * 16 + clB;
            gC0 = __ldg((const float2*)gp);
            gC1 = __ldg((const float2*)(gp + (size_t)8 * G3));
        }
#pragma unroll
        for (int i = 0; i < 8; i++) {
            u32 ch = (u32)(tid + i * NTHR) * 16u;
            CP16(A1u + ch, g_r1[dir] + ch);
            CP16(A2u + ch, g_r2[dir] + ch);
        }
        CP_COMMIT();
        CP_WAIT0();
        __syncthreads();

        {
            float dhh[4] = {0, 0, 0, 0}, dhl[4] = {0, 0, 0, 0}, dlh[4] = {0, 0, 0, 0};
#pragma unroll 4
            for (int ks = 0; ks < 16; ks++) {
                int kk = khB * 16 + ks;
                u32 ca = (u32)(2 * kk) + kq4;
                u32 cas = (ca & ~7u) | ((ca ^ rxAB) & 7u);
                u32 aH[4], aL[4], bH[2], bL[2];
                ldm4(aH, A1u + bRow + cas * 16u);
                ldm4(aL, A2u + bRow + cas * 16u);
                u32 cb = (u32)(2 * kk) + kq2;
                u32 cbs = (cb & ~7u) | ((cb ^ rxV) & 7u);
                ldm2(bH, V1u + vRow + cbs * 16u);
                ldm2(bL, V2u + vRow + cbs * 16u);
                mma_bf16(dhh, aH, bH);
                mma_bf16(dhl, aH, bL);
                mma_bf16(dlh, aL, bH);
            }
            float p0 = dhh[0] + dhl[0] + dlh[0];
            float p1 = dhh[1] + dhl[1] + dlh[1];
            float p2 = dhh[2] + dhl[2] + dlh[2];
            float p3 = dhh[3] + dhl[3] + dlh[3];

            __syncthreads();       // all A-image ldm reads complete
            if (khB == 1) {        // write partials into dead A region
                sPf[erB * 16 + clB]           = p0;
                sPf[erB * 16 + clB + 1]       = p1;
                sPf[(erB + 8) * 16 + clB]     = p2;
                sPf[(erB + 8) * 16 + clB + 1] = p3;
            }
            __syncthreads();
            if (khB == 0) {
                float zv[4];
                zv[0] = p0 + sPf[erB * 16 + clB];
                zv[1] = p1 + sPf[erB * 16 + clB + 1];
                zv[2] = p2 + sPf[(erB + 8) * 16 + clB];
                zv[3] = p3 + sPf[(erB + 8) * 16 + clB + 1];
                float gcx[4] = {gC0.x, gC0.y, gC1.x, gC1.y};
                float bcx[4] = {biasC.x, biasC.y, biasC.x, biasC.y};
                u16 p_hi[4], p_lo[4];
                float hn[4];
#pragma unroll
                for (int q = 0; q < 4; q++) {
                    float hh = tanhf(zv[q] + gcx[q] + bcx[q]);
                    hn[q] = holdreg[q] + ureg[q] * (hh - holdreg[q]);
                    split_bf16(hn[q], p_hi[q], p_lo[q]);
                }
                float* op0 = out + ((size_t)erB * T_ + t) * 1024 + dir * 512 + rank * 16 + clB;
                float* op1 = out + ((size_t)(erB + 8) * T_ + t) * 1024 + dir * 512 + rank * 16 + clB;
                *(float2*)op0 = make_float2(hn[0], hn[1]);
                *(float2*)op1 = make_float2(hn[2], hn[3]);
                u32 kc = (u32)(rank * 16 + clB);
                u32 o0 = off_((u32)erB, kc);
                u32 o1 = off_((u32)(erB + 8), kc);
                *(u32*)(g_h1[dir] + o0) = (u32)p_hi[0] | ((u32)p_hi[1] << 16);
                *(u32*)(g_h2[dir] + o0) = (u32)p_lo[0] | ((u32)p_lo[1] << 16);
                *(u32*)(g_h1[dir] + o1) = (u32)p_hi[2] | ((u32)p_hi[3] << 16);
                *(u32*)(g_h2[dir] + o1) = (u32)p_lo[2] | ((u32)p_lo[3] << 16);
            }
        }
        dir_barrier(dir);
    }
}

// =====================================================================
extern "C" void kernel_launch(void* const* d_in, const int* in_sizes, int n_in,
                              void* d_out, int out_size)
{
    const float* x   = (const float*)d_in[0];
    const float* Wxf = (const float*)d_in[1];
    const float* Whf = (const float*)d_in[2];
    const float* bf  = (const float*)d_in[3];
    const float* Wxb = (const float*)d_in[4];
    const float* Whb = (const float*)d_in[5];
    const float* bb  = (const float*)d_in[6];
    float* out = (float*)d_out;

    cudaFuncSetAttribute(k_scan, cudaFuncAttributeMaxDynamicSharedMemorySize, SCAN_SMEM);
    cudaFuncSetAttribute(k_inproj_mma, cudaFuncAttributeMaxDynamicSharedMemorySize, INPROJ_SMEM);

    k_split_x<<<4096, 256>>>(x);
    k_split_w<<<12, 256>>>(Wxf, Wxb);
    dim3 gI(256, 48);
    k_inproj_mma<<<gI, NTHR, INPROJ_SMEM>>>(0);
    k_scan<<<NBLK, NTHR, SCAN_SMEM>>>(Whf, Whb, bf, bb, out);
}

// round 17
// speedup vs baseline: 1.2145x; 1.2145x over previous
#include <cuda_runtime.h>
#include <cuda_bf16.h>

typedef unsigned int u32;
typedef unsigned short u16;

#define B_   64
#define T_   512
#define D_   256
#define U_   512
#define G3   1536
#define NBLK 128
#define NTHR 512
#define SCAN_SMEM 181248
#define INPROJ_SMEM 98304

// ---------------- device scratch (no allocations allowed) ----------------
__device__ float g_gx[(size_t)2 * T_ * B_ * G3];   // [dir][t][b][3U]
// bf16-split state images (ldmatrix-swizzled): [dir][64KB]
__device__ __align__(16) unsigned char g_h1[2][65536];
__device__ __align__(16) unsigned char g_h2[2][65536];
__device__ __align__(16) unsigned char g_r1[2][65536];
__device__ __align__(16) unsigned char g_r2[2][65536];
// bf16-split inproj operand images
__device__ __align__(16) unsigned char g_x1[(size_t)32768 * 512];  // 16MB
__device__ __align__(16) unsigned char g_x2[(size_t)32768 * 512];
__device__ __align__(16) unsigned char g_w1[(size_t)3072 * 512];   // 1.5MB
__device__ __align__(16) unsigned char g_w2[(size_t)3072 * 512];
// distributed-flag barrier state (zeroed at end of each launch -> replay-safe)
__device__ volatile unsigned g_flag[2][64];
__device__ volatile unsigned g_rel[2];
// legacy atomic barrier (self-resetting) for end-of-launch cleanup
__device__ unsigned          g_barc[2] = {0, 0};
__device__ volatile unsigned g_barg[2] = {0, 0};

// Fast barrier: parallel arrivals to per-rank slots, rank0 aggregates.
__device__ __forceinline__ void dir_barrier_tick(int dir, int rank, unsigned tick) {
    __syncthreads();
    if (threadIdx.x == 0) {
        __threadfence();
        g_flag[dir][rank] = tick;
    }
    if (rank == 0) {
        if (threadIdx.x < 32) {
            int i0 = (int)threadIdx.x << 1;
            while (g_flag[dir][i0] < tick) { }
            while (g_flag[dir][i0 + 1] < tick) { }
            __syncwarp();
            if (threadIdx.x == 0) { __threadfence(); g_rel[dir] = tick; }
        }
    } else if (threadIdx.x == 0) {
        while (g_rel[dir] < tick) { }
    }
    __syncthreads();
}

// Legacy atomic barrier (R2-proven) — used once at end for flag reset.
__device__ __forceinline__ void dir_barrier_legacy(int dir) {
    __threadfence();
    __syncthreads();
    if (threadIdx.x == 0) {
        unsigned g = g_barg[dir];
        unsigned prev = atomicAdd(&g_barc[dir], 1u);
        if (prev == 63u) {
            g_barc[dir] = 0u;
            __threadfence();
            g_barg[dir] = g + 1u;
        } else {
            while (g_barg[dir] == g) { }
        }
    }
    __syncthreads();
}

__device__ __forceinline__ float sigmoidf_(float z) {
    return 1.0f / (1.0f + __expf(-z));
}
__device__ __forceinline__ u32 smem_u32(const void* p) {
    u32 a;
    asm("{ .reg .u64 t; cvta.to.shared.u64 t, %1; cvt.u32.u64 %0, t; }"
        : "=r"(a) : "l"(p));
    return a;
}
// 1KB-row image offset (512 bf16/row), XOR swizzle on 16B chunks
__device__ __forceinline__ u32 off_(u32 row, u32 k) {
    u32 c = k >> 3;
    c = (c & ~7u) | ((c ^ row) & 7u);
    return row * 1024u + c * 16u + (k & 7u) * 2u;
}
// 512B-row image (256 bf16/row)
__device__ __forceinline__ u32 off512_(u32 row, u32 k) {
    u32 c = k >> 3;
    c = (c & ~7u) | ((c ^ row) & 7u);
    return row * 512u + c * 16u + (k & 7u) * 2u;
}
__device__ __forceinline__ void ldm4(u32* r, u32 addr) {
    asm volatile("ldmatrix.sync.aligned.m8n8.x4.shared.b16 {%0,%1,%2,%3}, [%4];"
        : "=r"(r[0]), "=r"(r[1]), "=r"(r[2]), "=r"(r[3]) : "r"(addr));
}
__device__ __forceinline__ void ldm2(u32* r, u32 addr) {
    asm volatile("ldmatrix.sync.aligned.m8n8.x2.shared.b16 {%0,%1}, [%2];"
        : "=r"(r[0]), "=r"(r[1]) : "r"(addr));
}
__device__ __forceinline__ void mma_bf16(float* d, const u32* a, const u32* b) {
    asm volatile("mma.sync.aligned.m16n8k16.row.col.f32.bf16.bf16.f32 "
        "{%0,%1,%2,%3}, {%4,%5,%6,%7}, {%8,%9}, {%0,%1,%2,%3};"
        : "+f"(d[0]), "+f"(d[1]), "+f"(d[2]), "+f"(d[3])
        : "r"(a[0]), "r"(a[1]), "r"(a[2]), "r"(a[3]), "r"(b[0]), "r"(b[1]));
}
__device__ __forceinline__ void split_bf16(float x, u16& hi, u16& lo) {
    __nv_bfloat16 h = __float2bfloat16(x);
    __nv_bfloat16 l = __float2bfloat16(x - __bfloat162float(h));
    hi = __bfloat16_as_ushort(h);
    lo = __bfloat16_as_ushort(l);
}
__device__ __forceinline__ float join_bf16(const void* p1, const void* p2) {
    return __bfloat162float(__ushort_as_bfloat16(*(const u16*)p1)) +
           __bfloat162float(__ushort_as_bfloat16(*(const u16*)p2));
}
#define CP16(dst, src) \
    asm volatile("cp.async.cg.shared.global [%0], [%1], 16;" :: "r"(dst), "l"(src) : "memory")
#define CP_COMMIT() asm volatile("cp.async.commit_group;" ::: "memory")
template<int N> __device__ __forceinline__ void cp_waitN() {
    asm volatile("cp.async.wait_group %0;" :: "n"(N) : "memory");
}

// =====================================================================
// Prep kernels: split x and [Wx_f | Wx_b] into bf16 hi/lo images.
// =====================================================================
__global__ void __launch_bounds__(256) k_split_x(const float* __restrict__ x)
{
    int idx = blockIdx.x * 256 + threadIdx.x;
    int m = idx >> 5, c = idx & 31, k0 = c * 8;
    const float* src = x + (size_t)m * 256 + k0;
    float4 f0 = __ldg((const float4*)src);
    float4 f1 = __ldg((const float4*)(src + 4));
    float e[8] = {f0.x, f0.y, f0.z, f0.w, f1.x, f1.y, f1.z, f1.w};
    u16 h[8], l[8];
#pragma unroll
    for (int j = 0; j < 8; j++) split_bf16(e[j], h[j], l[j]);
    uint4 H = make_uint4(h[0] | (h[1] << 16), h[2] | (h[3] << 16),
                         h[4] | (h[5] << 16), h[6] | (h[7] << 16));
    uint4 L = make_uint4(l[0] | (l[1] << 16), l[2] | (l[3] << 16),
                         l[4] | (l[5] << 16), l[6] | (l[7] << 16));
    u32 o = off512_((u32)m, (u32)k0);
    *(uint4*)(g_x1 + o) = H;
    *(uint4*)(g_x2 + o) = L;
}

__global__ void __launch_bounds__(256) k_split_w(
    const float* __restrict__ Wxf, const float* __restrict__ Wxb)
{
    int n = blockIdx.x * 256 + threadIdx.x;
    int dir = (n >= G3) ? 1 : 0;
    int col = n - dir * G3;
    const float* W = dir ? Wxb : Wxf;
    for (int c = 0; c < 32; c++) {
        u16 h[8], l[8];
#pragma unroll
        for (int j = 0; j < 8; j++)
            split_bf16(__ldg(W + (size_t)(c * 8 + j) * G3 + col), h[j], l[j]);
        uint4 H = make_uint4(h[0] | (h[1] << 16), h[2] | (h[3] << 16),
                             h[4] | (h[5] << 16), h[6] | (h[7] << 16));
        uint4 L = make_uint4(l[0] | (l[1] << 16), l[2] | (l[3] << 16),
                             l[4] | (l[5] << 16), l[6] | (l[7] << 16));
        u32 o = off512_((u32)n, (u32)(c * 8));
        *(uint4*)(g_w1 + o) = H;
        *(uint4*)(g_w2 + o) = L;
    }
}

// =====================================================================
// Kernel A: input projections via bf16-split HMMA (R12-proven).
// =====================================================================
extern __shared__ char ipsm[];

__global__ void __launch_bounds__(NTHR, 1) k_inproj_mma(int dummy)
{
    const int tid  = threadIdx.x;
    const int wid  = tid >> 5;
    const int lane = tid & 31;
    const int m0   = blockIdx.x * 128;
    const int n0   = blockIdx.y * 64;
    const int wm   = wid & 3, wn = wid >> 2;

    const u32 sbase = smem_u32(ipsm);
    auto stage_load = [&](int kt, int s) {
        u32 b0 = sbase + (u32)s * 49152u;
#pragma unroll
        for (int i = 0; i < 6; i++) {
            int gid = tid + i * NTHR;
            if (gid < 2048) {
                int term = gid >> 10, row = (gid & 1023) >> 3, c = gid & 7;
                u32 dst = b0 + (u32)term * 16384u + (u32)(row * 128 + c * 16);
                const unsigned char* srcimg = term ? g_x2 : g_x1;
                CP16(dst, srcimg + (size_t)(m0 + row) * 512 + kt * 128 + c * 16);
            } else {
                int g2 = gid - 2048;
                int term = g2 >> 9, row = (g2 & 511) >> 3, c = g2 & 7;
                u32 dst = b0 + 32768u + (u32)term * 8192u + (u32)(row * 128 + c * 16);
                const unsigned char* srcimg = term ? g_w2 : g_w1;
                CP16(dst, srcimg + (size_t)(n0 + row) * 512 + kt * 128 + c * 16);
            }
        }
        CP_COMMIT();
    };

    float dhh[2][2][4], dlo[2][2][4];
#pragma unroll
    for (int mi = 0; mi < 2; mi++)
#pragma unroll
        for (int ni = 0; ni < 2; ni++)
#pragma unroll
            for (int q = 0; q < 4; q++) { dhh[mi][ni][q] = 0.f; dlo[mi][ni][q] = 0.f; }

    stage_load(0, 0);
    stage_load(1, 1);

    const u32 rA0 = (u32)(wm * 32 + (lane & 15));
    const u32 rA1 = rA0 + 16;
    const u32 nB0 = (u32)(wn * 16 + (lane & 7));
    const u32 nB1 = nB0 + 8;
    const u32 kq4 = (u32)(lane >> 4);
    const u32 kq2 = (u32)((lane >> 3) & 1);

    for (int kt = 0; kt < 4; kt++) {
        if (kt < 3) cp_waitN<1>(); else cp_waitN<0>();
        __syncthreads();
        u32 b0 = sbase + (u32)(kt & 1) * 49152u;
        u32 AhU = b0, AlU = b0 + 16384u, BhU = b0 + 32768u, BlU = b0 + 40960u;
#pragma unroll
        for (int ks = 0; ks < 4; ks++) {
            u32 ca = (u32)(2 * ks) + kq4;
            u32 ca0 = (ca ^ rA0) & 7u, ca1 = (ca ^ rA1) & 7u;
            u32 aH0[4], aH1[4], aL0[4], aL1[4];
            ldm4(aH0, AhU + rA0 * 128u + ca0 * 16u);
            ldm4(aH1, AhU + rA1 * 128u + ca1 * 16u);
            ldm4(aL0, AlU + rA0 * 128u + ca0 * 16u);
            ldm4(aL1, AlU + rA1 * 128u + ca1 * 16u);
            u32 cb = (u32)(2 * ks) + kq2;
            u32 cb0 = (cb ^ nB0) & 7u, cb1 = (cb ^ nB1) & 7u;
            u32 bH0[2], bH1[2], bL0[2], bL1[2];
            ldm2(bH0, BhU + nB0 * 128u + cb0 * 16u);
            ldm2(bH1, BhU + nB1 * 128u + cb1 * 16u);
            ldm2(bL0, BlU + nB0 * 128u + cb0 * 16u);
            ldm2(bL1, BlU + nB1 * 128u + cb1 * 16u);
            mma_bf16(dhh[0][0], aH0, bH0); mma_bf16(dhh[0][1], aH0, bH1);
            mma_bf16(dhh[1][0], aH1, bH0); mma_bf16(dhh[1][1], aH1, bH1);
            mma_bf16(dlo[0][0], aH0, bL0); mma_bf16(dlo[0][1], aH0, bL1);
            mma_bf16(dlo[1][0], aH1, bL0); mma_bf16(dlo[1][1], aH1, bL1);
            mma_bf16(dlo[0][0], aL0, bH0); mma_bf16(dlo[0][1], aL0, bH1);
            mma_bf16(dlo[1][0], aL1, bH0); mma_bf16(dlo[1][1], aL1, bH1);
        }
        __syncthreads();
        if (kt < 2) stage_load(kt + 2, kt & 1);
    }

#pragma unroll
    for (int mi = 0; mi < 2; mi++)
#pragma unroll
        for (int ni = 0; ni < 2; ni++) {
            int gm = m0 + wm * 32 + mi * 16 + (lane >> 2);
            int gc = n0 + wn * 16 + ni * 8 + (lane & 3) * 2;
            int dir = (gc >= G3) ? 1 : 0;
            int cc  = gc - dir * G3;
            int b   = gm >> 9;
#pragma unroll
            for (int half = 0; half < 2; half++) {
                int s = (gm + half * 8) & 511;
                int tt = dir ? (T_ - 1 - s) : s;
                float* d = g_gx + (((size_t)dir * T_ + tt) * B_ + b) * G3 + cc;
                *(float2*)d = make_float2(dhh[mi][ni][half * 2] + dlo[mi][ni][half * 2],
                                          dhh[mi][ni][half * 2 + 1] + dlo[mi][ni][half * 2 + 1]);
            }
        }
}

// =====================================================================
// Kernel B: persistent HMMA scan (R12 structure + flag barrier +
// 4-group pipelined staging). 128 blocks (64/dir), 512 thr.
// =====================================================================
extern __shared__ char dynsm[];

__global__ void __launch_bounds__(NTHR, 1)
k_scan(const float* __restrict__ Whf, const float* __restrict__ Whb,
       const float* __restrict__ bf,  const float* __restrict__ bb,
       float* __restrict__ out)
{
    __shared__ float sP[1024];     // cross-k-half partials

    const int tid  = threadIdx.x;
    const int wid  = tid >> 5;
    const int lane = tid & 31;
    const int blk  = blockIdx.x;
    const int dir  = blk >> 6;
    const int rank = blk & 63;

    const float* __restrict__ Wh   = dir ? Whb : Whf;
    const float* __restrict__ bias = dir ? bb : bf;

    const u32 raw  = smem_u32(dynsm);
    const u32 base = (raw + 1023u) & ~1023u;
    char* dp = dynsm + (base - raw);
    char* A1 = dp;                 // 64KB state hi
    char* A2 = dp + 65536;         // 64KB state lo
    char* W1 = dp + 131072;        // 16KB phase-A weights hi (16 rows)
    char* W2 = dp + 147456;
    char* V1 = dp + 163840;        //  8KB phase-B weights hi (8 rows)
    char* V2 = dp + 172032;
    const u32 A1u = base, A2u = base + 65536;
    const u32 W1u = base + 131072, W2u = base + 147456;
    const u32 V1u = base + 163840, V2u = base + 172032;

    // ---- split weight slices into smem (once) ----
    for (int i = tid; i < 16 * 512; i += NTHR) {
        int n = i >> 9, k = i & 511;
        int col = (n < 8) ? (rank * 8 + n) : (512 + rank * 8 + (n - 8));
        u16 hi, lo;
        split_bf16(__ldg(Wh + (size_t)k * G3 + col), hi, lo);
        u32 o = off_((u32)n, (u32)k);
        *(u16*)(W1 + o) = hi;
        *(u16*)(W2 + o) = lo;
    }
    for (int i = tid; i < 8 * 512; i += NTHR) {
        int n = i >> 9, k = i & 511;
        u16 hi, lo;
        split_bf16(__ldg(Wh + (size_t)k * G3 + 1024 + rank * 8 + n), hi, lo);
        u32 o = off_((u32)n, (u32)k);
        *(u16*)(V1 + o) = hi;
        *(u16*)(V2 + o) = lo;
    }

    // ---- pipelined staging helper: group g = k range [128g, 128g+128) ----
    auto stage_group = [&](const unsigned char* s1, const unsigned char* s2, int g) {
#pragma unroll
        for (int i = 0; i < 2; i++) {
            int cid = tid + i * NTHR;               // 0..1023
            u32 off = (u32)((cid >> 4) * 1024 + (g << 8) + (cid & 15) * 16);
            CP16(A1u + off, s1 + off);
            CP16(A2u + off, s2 + off);
        }
        CP_COMMIT();
    };

    // ---- warp mappings ----
    // Phase A: 16 warps = 2 k-halves x (4m x 2n)
    const int khA = wid >> 3;
    const int ws  = wid & 7;
    const int mt  = ws & 3, nt = ws >> 2;
    const u32 rA   = (u32)(mt * 16 + (lane & 15));
    const u32 aRow = rA * 1024u;
    const u32 rxA  = rA & 7u;
    const u32 nA   = (u32)(nt * 8 + (lane & 7));
    const u32 nRow = nA * 1024u;
    const u32 rxB  = nA & 7u;
    const u32 kq4  = (u32)(lane >> 4);
    const u32 kq2  = (u32)((lane >> 3) & 1);
    // Phase B: warps 0-7 = 2 k-halves x 4m
    const int khB = (wid >> 2) & 1;
    const int mtB = wid & 3;
    const u32 rB   = (u32)(mtB * 16 + (lane & 15));
    const u32 bRow = rB * 1024u;
    const u32 rxAB = rB & 7u;
    const u32 nV   = (u32)(lane & 7);
    const u32 vRow = nV * 1024u;
    const u32 rxV  = nV & 7u;

    // epilogue rows/cols
    const int er0 = mt * 16 + (lane >> 2);      // phase A rows (+8)
    const int ec0 = (lane & 3) * 2;
    const int erB = mtB * 16 + (lane >> 2);     // phase B rows (+8)

    const int gbaseA = (nt ? 512 : 0) + rank * 8 + ec0;
    float2 biasA = make_float2(0.f, 0.f), biasC = make_float2(0.f, 0.f);
    if (wid < 8) biasA = *(const float2*)(bias + gbaseA);
    if (wid < 4) biasC = *(const float2*)(bias + 1024 + rank * 8 + ec0);

    float ureg[4], holdreg[4];
    const float* gx0 = g_gx + (size_t)dir * T_ * B_ * G3;
    unsigned tick = 1;

    for (int t = 0; t < T_; t++) {
        const float* gxt = gx0 + (size_t)t * B_ * G3;

        // ================= Phase A =================
        float2 gA0, gA1;
        if (wid < 8) {
            const float* gp = gxt + (size_t)er0 * G3 + gbaseA;
            gA0 = __ldg((const float2*)gp);
            gA1 = __ldg((const float2*)(gp + (size_t)8 * G3));
        }
        if (t == 0) {
            uint4 z0 = make_uint4(0, 0, 0, 0);
#pragma unroll
            for (int i = 0; i < 8; i++) {
                int idx = tid + i * NTHR;
                ((uint4*)A1)[idx] = z0;
                ((uint4*)A2)[idx] = z0;
            }
        } else {
            stage_group(g_h1[dir], g_h2[dir], 0);
            stage_group(g_h1[dir], g_h2[dir], 1);
            stage_group(g_h1[dir], g_h2[dir], 2);
            stage_group(g_h1[dir], g_h2[dir], 3);
        }

        float dhh[4] = {0, 0, 0, 0}, dhl[4] = {0, 0, 0, 0}, dlh[4] = {0, 0, 0, 0};
#pragma unroll
        for (int g = 0; g < 4; g++) {
            if (g == 0) cp_waitN<3>(); else if (g == 1) cp_waitN<2>();
            else if (g == 2) cp_waitN<1>(); else cp_waitN<0>();
            __syncthreads();
#pragma unroll
            for (int j = 0; j < 4; j++) {
                int kk = (g << 3) + (khA << 2) + j;
                u32 ca = (u32)(2 * kk) + kq4;
                u32 cas = (ca & ~7u) | ((ca ^ rxA) & 7u);
                u32 aH[4], aL[4], bH[2], bL[2];
                ldm4(aH, A1u + aRow + cas * 16u);
                ldm4(aL, A2u + aRow + cas * 16u);
                u32 cb = (u32)(2 * kk) + kq2;
                u32 cbs = (cb & ~7u) | ((cb ^ rxB) & 7u);
                ldm2(bH, W1u + nRow + cbs * 16u);
                ldm2(bL, W2u + nRow + cbs * 16u);
                mma_bf16(dhh, aH, bH);
                mma_bf16(dhl, aH, bL);
                mma_bf16(dlh, aL, bH);
            }
        }

        if (wid < 4) {   // hold extraction (full image now resident)
            u32 kc = (u32)(rank * 8 + ec0);
            u32 o0 = off_((u32)erB, kc), o1 = off_((u32)(erB + 8), kc);
            holdreg[0] = join_bf16(A1 + o0, A2 + o0);
            holdreg[1] = join_bf16(A1 + o0 + 2, A2 + o0 + 2);
            holdreg[2] = join_bf16(A1 + o1, A2 + o1);
            holdreg[3] = join_bf16(A1 + o1 + 2, A2 + o1 + 2);
        }

        if (khA == 1) {
            sP[er0 * 16 + nt * 8 + ec0]           = dhh[0] + dhl[0] + dlh[0];
            sP[er0 * 16 + nt * 8 + ec0 + 1]       = dhh[1] + dhl[1] + dlh[1];
            sP[(er0 + 8) * 16 + nt * 8 + ec0]     = dhh[2] + dhl[2] + dlh[2];
            sP[(er0 + 8) * 16 + nt * 8 + ec0 + 1] = dhh[3] + dhl[3] + dlh[3];
        }
        __syncthreads();
        if (khA == 0) {
            float z0v = dhh[0] + dhl[0] + dlh[0] + sP[er0 * 16 + nt * 8 + ec0];
            float z1v = dhh[1] + dhl[1] + dlh[1] + sP[er0 * 16 + nt * 8 + ec0 + 1];
            float z2v = dhh[2] + dhl[2] + dlh[2] + sP[(er0 + 8) * 16 + nt * 8 + ec0];
            float z3v = dhh[3] + dhl[3] + dlh[3] + sP[(er0 + 8) * 16 + nt * 8 + ec0 + 1];
            if (nt == 0) {       // u gates -> registers
                ureg[0] = sigmoidf_(z0v + gA0.x + biasA.x);
                ureg[1] = sigmoidf_(z1v + gA0.y + biasA.y);
                ureg[2] = sigmoidf_(z2v + gA1.x + biasA.x);
                ureg[3] = sigmoidf_(z3v + gA1.y + biasA.y);
            } else {             // r gates -> rh image
                float r0v = sigmoidf_(z0v + gA0.x + biasA.x);
                float r1v = sigmoidf_(z1v + gA0.y + biasA.y);
                float r2v = sigmoidf_(z2v + gA1.x + biasA.x);
                float r3v = sigmoidf_(z3v + gA1.y + biasA.y);
                u32 krh = (u32)(rank * 8 + ec0);
                u32 o0 = off_((u32)er0, krh);
                u32 o1 = off_((u32)(er0 + 8), krh);
                float h00 = join_bf16(A1 + o0, A2 + o0);
                float h01 = join_bf16(A1 + o0 + 2, A2 + o0 + 2);
                float h10 = join_bf16(A1 + o1, A2 + o1);
                float h11 = join_bf16(A1 + o1 + 2, A2 + o1 + 2);
                u16 a_hi, a_lo, b_hi, b_lo;
                split_bf16(r0v * h00, a_hi, a_lo);
                split_bf16(r1v * h01, b_hi, b_lo);
                *(u32*)(g_r1[dir] + o0) = (u32)a_hi | ((u32)b_hi << 16);
                *(u32*)(g_r2[dir] + o0) = (u32)a_lo | ((u32)b_lo << 16);
                split_bf16(r2v * h10, a_hi, a_lo);
                split_bf16(r3v * h11, b_hi, b_lo);
                *(u32*)(g_r1[dir] + o1) = (u32)a_hi | ((u32)b_hi << 16);
                *(u32*)(g_r2[dir] + o1) = (u32)a_lo | ((u32)b_lo << 16);
            }
        }
        dir_barrier_tick(dir, rank, tick++);

        // ================= Phase B =================
        float2 gC0, gC1;
        if (wid < 4) {
            const float* gp = gxt + (size_t)erB * G3 + 1024 + rank * 8 + ec0;
            gC0 = __ldg((const float2*)gp);
            gC1 = __ldg((const float2*)(gp + (size_t)8 * G3));
        }
        stage_group(g_r1[dir], g_r2[dir], 0);
        stage_group(g_r1[dir], g_r2[dir], 1);
        stage_group(g_r1[dir], g_r2[dir], 2);
        stage_group(g_r1[dir], g_r2[dir], 3);

        float ehh[4] = {0, 0, 0, 0}, ehl[4] = {0, 0, 0, 0}, elh[4] = {0, 0, 0, 0};
#pragma unroll
        for (int g = 0; g < 4; g++) {
            if (g == 0) cp_waitN<3>(); else if (g == 1) cp_waitN<2>();
            else if (g == 2) cp_waitN<1>(); else cp_waitN<0>();
            __syncthreads();
            if (wid < 8) {
#pragma unroll
                for (int j = 0; j < 4; j++) {
                    int kk = (g << 3) + (khB << 2) + j;
                    u32 ca = (u32)(2 * kk) + kq4;
                    u32 cas = (ca & ~7u) | ((ca ^ rxAB) & 7u);
                    u32 aH[4], aL[4], bH[2], bL[2];
                    ldm4(aH, A1u + bRow + cas * 16u);
                    ldm4(aL, A2u + bRow + cas * 16u);
                    u32 cb = (u32)(2 * kk) + kq2;
                    u32 cbs = (cb & ~7u) | ((cb ^ rxV) & 7u);
                    ldm2(bH, V1u + vRow + cbs * 16u);
                    ldm2(bL, V2u + vRow + cbs * 16u);
                    mma_bf16(ehh, aH, bH);
                    mma_bf16(ehl, aH, bL);
                    mma_bf16(elh, aL, bH);
                }
            }
        }

        if (wid < 8 && khB == 1) {
            sP[erB * 8 + ec0]           = ehh[0] + ehl[0] + elh[0];
            sP[erB * 8 + ec0 + 1]       = ehh[1] + ehl[1] + elh[1];
            sP[(erB + 8) * 8 + ec0]     = ehh[2] + ehl[2] + elh[2];
            sP[(erB + 8) * 8 + ec0 + 1] = ehh[3] + ehl[3] + elh[3];
        }
        __syncthreads();
        if (wid < 4) {
            float zv[4];
            zv[0] = ehh[0] + ehl[0] + elh[0] + sP[erB * 8 + ec0];
            zv[1] = ehh[1] + ehl[1] + elh[1] + sP[erB * 8 + ec0 + 1];
            zv[2] = ehh[2] + ehl[2] + elh[2] + sP[(erB + 8) * 8 + ec0];
            zv[3] = ehh[3] + ehl[3] + elh[3] + sP[(erB + 8) * 8 + ec0 + 1];
            float gcx[4] = {gC0.x, gC0.y, gC1.x, gC1.y};
            float bcx[4] = {biasC.x, biasC.y, biasC.x, biasC.y};
            u16 p_hi[4], p_lo[4];
            float hn[4];
#pragma unroll
            for (int q = 0; q < 4; q++) {
                float hh = tanhf(zv[q] + gcx[q] + bcx[q]);
                hn[q] = holdreg[q] + ureg[q] * (hh - holdreg[q]);
                split_bf16(hn[q], p_hi[q], p_lo[q]);
            }
            float* op0 = out + ((size_t)erB * T_ + t) * 1024 + dir * 512 + rank * 8 + ec0;
            float* op1 = out + ((size_t)(erB + 8) * T_ + t) * 1024 + dir * 512 + rank * 8 + ec0;
            *(float2*)op0 = make_float2(hn[0], hn[1]);
            *(float2*)op1 = make_float2(hn[2], hn[3]);
            u32 kc = (u32)(rank * 8 + ec0);
            u32 o0 = off_((u32)erB, kc);
            u32 o1 = off_((u32)(erB + 8), kc);
            *(u32*)(g_h1[dir] + o0) = (u32)p_hi[0] | ((u32)p_hi[1] << 16);
            *(u32*)(g_h2[dir] + o0) = (u32)p_lo[0] | ((u32)p_lo[1] << 16);
            *(u32*)(g_h1[dir] + o1) = (u32)p_hi[2] | ((u32)p_hi[3] << 16);
            *(u32*)(g_h2[dir] + o1) = (u32)p_lo[2] | ((u32)p_lo[3] << 16);
        }
        dir_barrier_tick(dir, rank, tick++);
    }

    // ---- reset flag-barrier state for next graph replay ----
    dir_barrier_legacy(dir);
    if (tid == 0) {
        g_flag[dir][rank] = 0;
        if (rank == 0) g_rel[dir] = 0;
    }
}

// =====================================================================
extern "C" void kernel_launch(void* const* d_in, const int* in_sizes, int n_in,
                              void* d_out, int out_size)
{
    const float* x   = (const float*)d_in[0];
    const float* Wxf = (const float*)d_in[1];
    const float* Whf = (const float*)d_in[2];
    const float* bf  = (const float*)d_in[3];
    const float* Wxb = (const float*)d_in[4];
    const float* Whb = (const float*)d_in[5];
    const float* bb  = (const float*)d_in[6];
    float* out = (float*)d_out;

    cudaFuncSetAttribute(k_scan, cudaFuncAttributeMaxDynamicSharedMemorySize, SCAN_SMEM);
    cudaFuncSetAttribute(k_inproj_mma, cudaFuncAttributeMaxDynamicSharedMemorySize, INPROJ_SMEM);

    k_split_x<<<4096, 256>>>(x);
    k_split_w<<<12, 256>>>(Wxf, Wxb);
    dim3 gI(256, 48);
    k_inproj_mma<<<gI, NTHR, INPROJ_SMEM>>>(0);
    k_scan<<<NBLK, NTHR, SCAN_SMEM>>>(Whf, Whb, bf, bb, out);
}